// round 6
// baseline (speedup 1.0000x reference)
#include <cuda_runtime.h>
#include <cuda_bf16.h>
#include <cstddef>

// Problem constants
#define BB    16
#define SS    4096
#define DD    1024      // D_IN
#define HH    1024
#define DOUT  1024
#define SPLIT 64
#define ROWS  (SS / SPLIT)   // 64 rows per pass1 block

// GEMV tiling
#define KS    8                    // grid K-splits
#define CHK   (DD / KS)            // 128 k per chunk
#define CF4   (CHK / 4)            // 32 float4 per chunk == warp width
#define NPW   2                    // n-rows per warp
#define NPB   (8 * NPW)            // 16 n-rows per block

// Scratch: __device__ globals (no cudaMalloc allowed)
__device__ float g_partial[BB * SPLIT * DD];   // pass1 partials, 4 MB
__device__ float g_m4[4 * BB * DD];            // pass2a partials, 256 KB
__device__ float g_m[BB * DD];                 // mean, 64 KB
__device__ float g_enc[BB * HH];               // hidden, 64 KB
__device__ float g_pA[KS * BB * HH];           // gemvA partials, 512 KB
__device__ float g_pB[KS * BB * DOUT];         // gemvB partials, 512 KB

// ---------------------------------------------------------------------------
// Pass 1: partial sums over S. grid = (SPLIT, B) = (64,16), block = 256.
// ---------------------------------------------------------------------------
__global__ __launch_bounds__(256) void pass1_kernel(const float* __restrict__ x) {
    const int split = blockIdx.x;
    const int b     = blockIdx.y;
    const int t     = threadIdx.x;

    const float4* xp = reinterpret_cast<const float4*>(
        x + ((size_t)b * SS + (size_t)split * ROWS) * DD);

    float4 acc = make_float4(0.f, 0.f, 0.f, 0.f);
    #pragma unroll 16
    for (int r = 0; r < ROWS; ++r) {
        float4 v = __ldcs(&xp[(size_t)r * (DD / 4) + t]);
        acc.x += v.x; acc.y += v.y; acc.z += v.z; acc.w += v.w;
    }

    float4* out = reinterpret_cast<float4*>(
        g_partial + ((size_t)b * SPLIT + split) * DD);
    out[t] = acc;
}

// ---------------------------------------------------------------------------
// Pass 2a: reduce 64 partials in 4 groups of 16 -> g_m4. grid (64,4) x 256.
// ---------------------------------------------------------------------------
__global__ __launch_bounds__(256) void pass2a_kernel() {
    const int idx = blockIdx.x * 256 + threadIdx.x;   // over B*D = 16384
    const int kp  = blockIdx.y;                        // 0..3
    const int b = idx / DD;
    const int d = idx % DD;

    const float* p = g_partial + (size_t)b * SPLIT * DD + (size_t)kp * 16 * DD + d;
    float s = 0.f;
    #pragma unroll
    for (int i = 0; i < 16; ++i) s += p[(size_t)i * DD];

    g_m4[(size_t)kp * (BB * DD) + idx] = s;
}

// ---------------------------------------------------------------------------
// Pass 2b: final 4-way reduce + 1/S scale -> g_m. 64 x 256.
// ---------------------------------------------------------------------------
__global__ __launch_bounds__(256) void pass2b_kernel() {
    const int idx = blockIdx.x * 256 + threadIdx.x;
    float s = g_m4[idx] + g_m4[idx + BB * DD] + g_m4[idx + 2 * BB * DD]
            + g_m4[idx + 3 * BB * DD];
    g_m[idx] = s * (1.0f / (float)SS);
}

// ---------------------------------------------------------------------------
// GEMV partial, lanes-along-K + butterfly reduce:
//   pout[ks][b][n] = sum_{k in chunk ks} v[b][k] * W[n][k]
// grid = (N/16, KS) = (64, 8) = 512 blocks, block = 256 (8 warps).
// Warp w owns n-rows {n0+2w, n0+2w+1}; lane = one float4 of the 128-k chunk.
// Per thread: 2 coalesced W float4 loads, 16 conflict-free LDS float4,
// 128 FFMA into acc[32], then a 31-shuffle recursive-halving reduce.
// After the reduce, lane L holds the finished output with original
// accumulator index == L  (n_local = L>>4, b = L&15).
// ---------------------------------------------------------------------------
__global__ __launch_bounds__(256) void gemv_kernel(
    const float* __restrict__ v,
    const float* __restrict__ W,
    float* __restrict__ pout)
{
    __shared__ float4 sV[BB * CF4];   // 16 b x 32 f4 = 8 KB

    const int t  = threadIdx.x;
    const int n0 = blockIdx.x * NPB;
    const int ks = blockIdx.y;

    // ---- fill v chunk: 512 float4, 2 per thread, coalesced ---------------
    {
        const float4* V4 = reinterpret_cast<const float4*>(v);
        #pragma unroll
        for (int i = 0; i < 2; ++i) {
            const int id = i * 256 + t;         // 0..511
            const int b  = id >> 5;
            const int k4 = id & 31;
            sV[id] = V4[(size_t)b * (DD / 4) + (size_t)ks * CF4 + k4];
        }
    }
    __syncthreads();

    const int warp = t >> 5;
    const int lane = t & 31;
    const int n    = n0 + warp * NPW;

    // W: 2 rows, coalesced across lanes
    const float4* W4 = reinterpret_cast<const float4*>(W);
    const size_t wbase = (size_t)ks * CF4 + lane;
    float4 w0 = W4[(size_t)(n    ) * (DD / 4) + wbase];
    float4 w1 = W4[(size_t)(n + 1) * (DD / 4) + wbase];

    // acc[i], i = n_local*16 + b
    float acc[32];
    #pragma unroll
    for (int i = 0; i < 32; ++i) acc[i] = 0.f;

    #pragma unroll
    for (int b = 0; b < BB; ++b) {
        float4 m4 = sV[b * CF4 + lane];
        acc[b]      += m4.x * w0.x + m4.y * w0.y + m4.z * w0.z + m4.w * w0.w;
        acc[16 + b] += m4.x * w1.x + m4.y * w1.y + m4.z * w1.z + m4.w * w1.w;
    }

    // ---- recursive-halving butterfly: 16+8+4+2+1 = 31 shuffles -----------
    #pragma unroll
    for (int step = 0; step < 5; ++step) {
        const int off = 16 >> step;
        const int m   = 32 >> step;
        const bool hi = (lane & off) != 0;
        #pragma unroll
        for (int i = 0; i < 32; ++i) {           // only i < m/2 active
            if (i < m / 2) {
                float tmp  = hi ? acc[i] : acc[i + m / 2];
                float recv = __shfl_xor_sync(0xffffffffu, tmp, off);
                acc[i] = (hi ? acc[i + m / 2] : acc[i]) + recv;
            }
        }
    }

    // lane holds acc[0] for (n_local = lane>>4, b = lane&15)
    const int b_out = lane & 15;
    const int n_out = n + (lane >> 4);
    pout[(size_t)ks * (BB * HH) + (size_t)b_out * HH + n_out] = acc[0];
}

// ---------------------------------------------------------------------------
// Reduce KS partial slices + bias. 64 x 256. out[b][n].
// ---------------------------------------------------------------------------
__global__ __launch_bounds__(256) void reduceks_kernel(
    const float* __restrict__ pin,
    const float* __restrict__ bias,
    float* __restrict__ out)
{
    const int idx = blockIdx.x * 256 + threadIdx.x;   // over B*N = 16384
    const int nn = idx & (HH - 1);
    float s = bias[nn];
    #pragma unroll
    for (int j = 0; j < KS; ++j) s += pin[(size_t)j * (BB * HH) + idx];
    out[idx] = s;
}

// ---------------------------------------------------------------------------
// Launch. Inputs (metadata order): x, W_enc, b_enc, W_out, b_out.
// ---------------------------------------------------------------------------
extern "C" void kernel_launch(void* const* d_in, const int* in_sizes, int n_in,
                              void* d_out, int out_size)
{
    const float* x     = (const float*)d_in[0];
    const float* W_enc = (const float*)d_in[1];
    const float* b_enc = (const float*)d_in[2];
    const float* W_out = (const float*)d_in[3];
    const float* b_out = (const float*)d_in[4];
    float*       out   = (float*)d_out;

    static float* p_m   = nullptr;
    static float* p_enc = nullptr;
    static float* p_pA  = nullptr;
    static float* p_pB  = nullptr;
    if (!p_m)   cudaGetSymbolAddress((void**)&p_m,   g_m);
    if (!p_enc) cudaGetSymbolAddress((void**)&p_enc, g_enc);
    if (!p_pA)  cudaGetSymbolAddress((void**)&p_pA,  g_pA);
    if (!p_pB)  cudaGetSymbolAddress((void**)&p_pB,  g_pB);

    // 1) partial sums over S
    pass1_kernel<<<dim3(SPLIT, BB), 256>>>(x);
    // 2) mean in two levels
    pass2a_kernel<<<dim3(64, 4), 256>>>();
    pass2b_kernel<<<64, 256>>>();
    // 3) enc = m @ W_enc^T + b_enc
    gemv_kernel<<<dim3(HH / NPB, KS), 256>>>(p_m, W_enc, p_pA);
    reduceks_kernel<<<64, 256>>>(p_pA, b_enc, p_enc);
    // 4) out = enc @ W_out^T + b_out
    gemv_kernel<<<dim3(DOUT / NPB, KS), 256>>>(p_enc, W_out, p_pB);
    reduceks_kernel<<<64, 256>>>(p_pB, b_out, out);
}

// round 7
// speedup vs baseline: 1.0023x; 1.0023x over previous
#include <cuda_runtime.h>
#include <cuda_bf16.h>
#include <cstddef>

// Problem constants
#define BB    16
#define SS    4096
#define DD    1024      // D_IN
#define HH    1024
#define DOUT  1024
#define SPLIT 64
#define ROWS  (SS / SPLIT)   // 64 rows per pass1 block

// GEMV tiling
#define KS    4                    // grid K-splits
#define CHK   (DD / KS)            // 256 k per chunk
#define CF4   (CHK / 4)            // 64 float4 per chunk
#define LF4   (CF4 / 32)           // 2 float4 per lane
#define NPW   2                    // n-rows per warp
#define NPB   (8 * NPW)            // 16 n-rows per block

// Scratch: __device__ globals (no cudaMalloc allowed)
__device__ float g_partial[BB * SPLIT * DD];   // pass1 partials, 4 MB
__device__ float g_m4[4 * BB * DD];            // pass2a partials, 256 KB
__device__ float g_m[BB * DD];                 // mean, 64 KB
__device__ float g_enc[BB * HH];               // hidden, 64 KB
__device__ float g_pA[KS * BB * HH];           // gemvA partials, 256 KB
__device__ float g_pB[KS * BB * DOUT];         // gemvB partials, 256 KB

// ---------------------------------------------------------------------------
// Pass 1: partial sums over S. grid = (SPLIT, B) = (64,16), block = 256.
// ---------------------------------------------------------------------------
__global__ __launch_bounds__(256) void pass1_kernel(const float* __restrict__ x) {
    const int split = blockIdx.x;
    const int b     = blockIdx.y;
    const int t     = threadIdx.x;

    const float4* xp = reinterpret_cast<const float4*>(
        x + ((size_t)b * SS + (size_t)split * ROWS) * DD);

    float4 acc = make_float4(0.f, 0.f, 0.f, 0.f);
    #pragma unroll 16
    for (int r = 0; r < ROWS; ++r) {
        float4 v = __ldcs(&xp[(size_t)r * (DD / 4) + t]);
        acc.x += v.x; acc.y += v.y; acc.z += v.z; acc.w += v.w;
    }

    float4* out = reinterpret_cast<float4*>(
        g_partial + ((size_t)b * SPLIT + split) * DD);
    out[t] = acc;
}

// ---------------------------------------------------------------------------
// Pass 2a: reduce 64 partials in 4 groups of 16 -> g_m4. grid (64,4) x 256.
// ---------------------------------------------------------------------------
__global__ __launch_bounds__(256) void pass2a_kernel() {
    const int idx = blockIdx.x * 256 + threadIdx.x;   // over B*D = 16384
    const int kp  = blockIdx.y;                        // 0..3
    const int b = idx / DD;
    const int d = idx % DD;

    const float* p = g_partial + (size_t)b * SPLIT * DD + (size_t)kp * 16 * DD + d;
    float s = 0.f;
    #pragma unroll
    for (int i = 0; i < 16; ++i) s += p[(size_t)i * DD];

    g_m4[(size_t)kp * (BB * DD) + idx] = s;
}

// ---------------------------------------------------------------------------
// Pass 2b: final 4-way reduce + 1/S scale -> g_m. 64 x 256.
// ---------------------------------------------------------------------------
__global__ __launch_bounds__(256) void pass2b_kernel() {
    const int idx = blockIdx.x * 256 + threadIdx.x;
    float s = g_m4[idx] + g_m4[idx + BB * DD] + g_m4[idx + 2 * BB * DD]
            + g_m4[idx + 3 * BB * DD];
    g_m[idx] = s * (1.0f / (float)SS);
}

// ---------------------------------------------------------------------------
// GEMV partial, lanes-along-K (2 f4 per lane) + butterfly reduce:
//   pout[ks][b][n] = sum_{k in chunk ks} v[b][k] * W[n][k]
// grid = (N/16, KS) = (64, 4) = 256 blocks, block = 256 (8 warps).
// Warp w owns n-rows {n0+2w, n0+2w+1}; lane covers float4 {lane, lane+32}
// of the 256-k chunk. Per thread: 4 coalesced W LDG.128, 32 LDS.128,
// 256 FFMA into acc[32], then the 31-shuffle recursive-halving reduce.
// After the reduce, lane L holds the output with original index == L
// (n_local = L>>4, b = L&15).
// ---------------------------------------------------------------------------
__global__ __launch_bounds__(256) void gemv_kernel(
    const float* __restrict__ v,
    const float* __restrict__ W,
    float* __restrict__ pout)
{
    __shared__ float4 sV[BB * CF4];   // 16 b x 64 f4 = 16 KB

    const int t  = threadIdx.x;
    const int n0 = blockIdx.x * NPB;
    const int ks = blockIdx.y;

    // ---- fill v chunk: 1024 float4, 4 per thread, coalesced --------------
    {
        const float4* V4 = reinterpret_cast<const float4*>(v);
        #pragma unroll
        for (int i = 0; i < 4; ++i) {
            const int id = i * 256 + t;         // 0..1023
            const int b  = id >> 6;
            const int k4 = id & 63;
            sV[id] = V4[(size_t)b * (DD / 4) + (size_t)ks * CF4 + k4];
        }
    }
    __syncthreads();

    const int warp = t >> 5;
    const int lane = t & 31;
    const int n    = n0 + warp * NPW;

    // W: 2 rows x 2 float4 per lane, coalesced across lanes
    const float4* W4 = reinterpret_cast<const float4*>(W);
    const size_t wbase = (size_t)ks * CF4 + lane;
    float4 w0a = W4[(size_t)(n    ) * (DD / 4) + wbase];
    float4 w0b = W4[(size_t)(n    ) * (DD / 4) + wbase + 32];
    float4 w1a = W4[(size_t)(n + 1) * (DD / 4) + wbase];
    float4 w1b = W4[(size_t)(n + 1) * (DD / 4) + wbase + 32];

    // acc[i], i = n_local*16 + b
    float acc[32];
    #pragma unroll
    for (int i = 0; i < 32; ++i) acc[i] = 0.f;

    #pragma unroll
    for (int b = 0; b < BB; ++b) {
        float4 ma = sV[b * CF4 + lane];
        float4 mb = sV[b * CF4 + lane + 32];
        acc[b]      += ma.x * w0a.x + ma.y * w0a.y + ma.z * w0a.z + ma.w * w0a.w
                     + mb.x * w0b.x + mb.y * w0b.y + mb.z * w0b.z + mb.w * w0b.w;
        acc[16 + b] += ma.x * w1a.x + ma.y * w1a.y + ma.z * w1a.z + ma.w * w1a.w
                     + mb.x * w1b.x + mb.y * w1b.y + mb.z * w1b.z + mb.w * w1b.w;
    }

    // ---- recursive-halving butterfly: 16+8+4+2+1 = 31 shuffles -----------
    #pragma unroll
    for (int step = 0; step < 5; ++step) {
        const int off = 16 >> step;
        const int m   = 32 >> step;
        const bool hi = (lane & off) != 0;
        #pragma unroll
        for (int i = 0; i < 32; ++i) {           // only i < m/2 active
            if (i < m / 2) {
                float tmp  = hi ? acc[i] : acc[i + m / 2];
                float recv = __shfl_xor_sync(0xffffffffu, tmp, off);
                acc[i] = (hi ? acc[i + m / 2] : acc[i]) + recv;
            }
        }
    }

    // lane holds acc[0] for (n_local = lane>>4, b = lane&15)
    const int b_out = lane & 15;
    const int n_out = n + (lane >> 4);
    pout[(size_t)ks * (BB * HH) + (size_t)b_out * HH + n_out] = acc[0];
}

// ---------------------------------------------------------------------------
// Reduce KS partial slices + bias. 64 x 256. out[b][n].
// ---------------------------------------------------------------------------
__global__ __launch_bounds__(256) void reduceks_kernel(
    const float* __restrict__ pin,
    const float* __restrict__ bias,
    float* __restrict__ out)
{
    const int idx = blockIdx.x * 256 + threadIdx.x;   // over B*N = 16384
    const int nn = idx & (HH - 1);
    float s = bias[nn];
    #pragma unroll
    for (int j = 0; j < KS; ++j) s += pin[(size_t)j * (BB * HH) + idx];
    out[idx] = s;
}

// ---------------------------------------------------------------------------
// Launch. Inputs (metadata order): x, W_enc, b_enc, W_out, b_out.
// ---------------------------------------------------------------------------
extern "C" void kernel_launch(void* const* d_in, const int* in_sizes, int n_in,
                              void* d_out, int out_size)
{
    const float* x     = (const float*)d_in[0];
    const float* W_enc = (const float*)d_in[1];
    const float* b_enc = (const float*)d_in[2];
    const float* W_out = (const float*)d_in[3];
    const float* b_out = (const float*)d_in[4];
    float*       out   = (float*)d_out;

    static float* p_m   = nullptr;
    static float* p_enc = nullptr;
    static float* p_pA  = nullptr;
    static float* p_pB  = nullptr;
    if (!p_m)   cudaGetSymbolAddress((void**)&p_m,   g_m);
    if (!p_enc) cudaGetSymbolAddress((void**)&p_enc, g_enc);
    if (!p_pA)  cudaGetSymbolAddress((void**)&p_pA,  g_pA);
    if (!p_pB)  cudaGetSymbolAddress((void**)&p_pB,  g_pB);

    // 1) partial sums over S
    pass1_kernel<<<dim3(SPLIT, BB), 256>>>(x);
    // 2) mean in two levels
    pass2a_kernel<<<dim3(64, 4), 256>>>();
    pass2b_kernel<<<64, 256>>>();
    // 3) enc = m @ W_enc^T + b_enc
    gemv_kernel<<<dim3(HH / NPB, KS), 256>>>(p_m, W_enc, p_pA);
    reduceks_kernel<<<64, 256>>>(p_pA, b_enc, p_enc);
    // 4) out = enc @ W_out^T + b_out
    gemv_kernel<<<dim3(DOUT / NPB, KS), 256>>>(p_enc, W_out, p_pB);
    reduceks_kernel<<<64, 256>>>(p_pB, b_out, out);
}